// round 6
// baseline (speedup 1.0000x reference)
#include <cuda_runtime.h>

#define BATCH    512
#define TLEN     2048
#define CH       34      // true channel count (2*17)
#define P        36      // padded homogeneous dim
#define PP       37      // kernel_b row pitch
#define GP       44      // gram smem pitch (words): 16B-aligned rows, conflict-free octets
#define TT       128     // t-tile for Gram phase
#define NTHREADS 256
#define NSPLIT   4       // t-splits for Gram kernel
#define TSPLIT   (TLEN / NSPLIT)
#define NBLK8    15      // upper-triangular 8x8 blocks over 40 (5x5 grid)
#define CTT      256     // kernel_c t-tile
#define CTH      128     // kernel_c threads (2 t per thread)
#define HPITCH   258     // kernel_c transposed-h pitch

typedef unsigned long long ull;

// Per-batch fused head matrix: W1f[b][16][35] (homogeneous: col 34 = bias)
__device__ float g_W1f[BATCH * 16 * 35];
// Partial Gram matrices, blocked: g_part2[b][s][blk(15)][32 ull = 8x8 floats]
__device__ ull g_part2[BATCH * NSPLIT * NBLK8 * 32];

// ---------------- packed f32x2 helpers (sm_103a FFMA2) ----------------------

__device__ __forceinline__ ull pack2(float lo, float hi) {
    ull r; asm("mov.b64 %0, {%1, %2};" : "=l"(r) : "f"(lo), "f"(hi)); return r;
}
__device__ __forceinline__ void unpack2(ull v, float& lo, float& hi) {
    asm("mov.b64 {%0, %1}, %2;" : "=f"(lo), "=f"(hi) : "l"(v));
}
__device__ __forceinline__ void fma2(ull& d, ull a, ull b) {
    asm("fma.rn.f32x2 %0, %1, %2, %0;" : "+l"(d) : "l"(a), "l"(b));
}

// ---------------- 36x36 shared-memory matmuls (216 active threads) ----------

__device__ __forceinline__ void mm_nn(float (*D)[PP], const float (*A)[PP],
                                      const float (*B)[PP], int tid) {
    if (tid < 216) {
        int r  = tid % P;
        int c0 = (tid / P) * 6;
        float a0 = 0.f, a1 = 0.f, a2 = 0.f, a3 = 0.f, a4 = 0.f, a5 = 0.f;
#pragma unroll
        for (int k = 0; k < P; k++) {
            float a = A[r][k];
            a0 += a * B[k][c0 + 0];
            a1 += a * B[k][c0 + 1];
            a2 += a * B[k][c0 + 2];
            a3 += a * B[k][c0 + 3];
            a4 += a * B[k][c0 + 4];
            a5 += a * B[k][c0 + 5];
        }
        D[r][c0 + 0] = a0; D[r][c0 + 1] = a1; D[r][c0 + 2] = a2;
        D[r][c0 + 3] = a3; D[r][c0 + 4] = a4; D[r][c0 + 5] = a5;
    }
    __syncthreads();
}

__device__ __forceinline__ void mm_nt(float (*D)[PP], const float (*A)[PP],
                                      const float (*B)[PP], int tid) {
    if (tid < 216) {
        int r  = tid % P;
        int c0 = (tid / P) * 6;
        float a0 = 0.f, a1 = 0.f, a2 = 0.f, a3 = 0.f, a4 = 0.f, a5 = 0.f;
#pragma unroll
        for (int k = 0; k < P; k++) {
            float a = A[r][k];
            a0 += a * B[c0 + 0][k];
            a1 += a * B[c0 + 1][k];
            a2 += a * B[c0 + 2][k];
            a3 += a * B[c0 + 3][k];
            a4 += a * B[c0 + 4][k];
            a5 += a * B[c0 + 5][k];
        }
        D[r][c0 + 0] = a0; D[r][c0 + 1] = a1; D[r][c0 + 2] = a2;
        D[r][c0 + 3] = a3; D[r][c0 + 4] = a4; D[r][c0 + 5] = a5;
    }
    __syncthreads();
}

__device__ __forceinline__ void stage_w(float (*W)[PP], const float* __restrict__ w,
                                        const float* __restrict__ bias, int tid) {
    for (int i = tid; i < P * PP; i += NTHREADS) {
        int r = i / PP, c = i % PP;
        float v = 0.f;
        if (r < CH && c < CH)       v = w[r * CH + c];
        else if (r < CH && c == CH) v = bias[r];
        else if (r == CH && c == CH) v = 1.f;
        W[r][c] = v;
    }
    __syncthreads();
}

// ---------------- Kernel GRAM: partial S over a t-split, 8x8 blocks ---------

__global__ void __launch_bounds__(NTHREADS, 2) kernel_gram(const float* __restrict__ x)
{
    __shared__ __align__(16) float Hs[TT][GP];

    int tid = threadIdx.x;
    int b   = blockIdx.x;
    int s   = blockIdx.y;

    int sub = tid & 15;
    int blk = tid >> 4;          // 0..15 (blk 15 duplicates 14, discarded)
    int blkc = (blk < NBLK8) ? blk : (NBLK8 - 1);
    int k = blkc, r = 0;
    while (k >= 5 - r) { k -= 5 - r; r++; }
    int br = r, bc = r + k;      // 8x8 block (br, bc), bc >= br, over 40-dim

    ull acc[32];
#pragma unroll
    for (int i = 0; i < 32; i++) acc[i] = 0ull;

    const float* xb = x + (size_t)b * 2 * TLEN * 17;
    int tbase = s * TSPLIT;

    for (int t0 = tbase; t0 < tbase + TSPLIT; t0 += TT) {
        __syncthreads();
        // coalesced float4 stage -> Hs[t][ch]
#pragma unroll
        for (int c = 0; c < 2; c++) {
            const float4* src = (const float4*)(xb + (size_t)c * TLEN * 17 + (size_t)t0 * 17);
            for (int j = tid; j < TT * 17 / 4; j += NTHREADS) {
                float4 v = src[j];
                int idx = 4 * j;
                int t = idx / 17, vv = idx - 17 * t;
                float comp[4] = {v.x, v.y, v.z, v.w};
#pragma unroll
                for (int e = 0; e < 4; e++) {
                    Hs[t][c * 17 + vv] = comp[e];
                    vv++; if (vv == 17) { vv = 0; t++; }
                }
            }
        }
        for (int i = tid; i < TT; i += NTHREADS) {
            Hs[i][34] = 1.f;
#pragma unroll
            for (int z = 35; z < 40; z++) Hs[i][z] = 0.f;
        }
        __syncthreads();

        for (int t = sub; t < TT; t += 16) {
            const float4* pa = (const float4*)&Hs[t][8 * br];
            float4 a0 = pa[0], a1 = pa[1];
            const ulonglong2* pb = (const ulonglong2*)&Hs[t][8 * bc];
            ulonglong2 b01 = pb[0], b23 = pb[1];
            ull sa[8];
            sa[0] = pack2(a0.x, a0.x); sa[1] = pack2(a0.y, a0.y);
            sa[2] = pack2(a0.z, a0.z); sa[3] = pack2(a0.w, a0.w);
            sa[4] = pack2(a1.x, a1.x); sa[5] = pack2(a1.y, a1.y);
            sa[6] = pack2(a1.z, a1.z); sa[7] = pack2(a1.w, a1.w);
#pragma unroll
            for (int i = 0; i < 8; i++) {
                fma2(acc[i * 4 + 0], sa[i], b01.x);
                fma2(acc[i * 4 + 1], sa[i], b01.y);
                fma2(acc[i * 4 + 2], sa[i], b23.x);
                fma2(acc[i * 4 + 3], sa[i], b23.y);
            }
        }
    }

    // reduce the 16 t-phases within each 16-lane group (all lanes participate)
#pragma unroll
    for (int off = 8; off >= 1; off >>= 1) {
#pragma unroll
        for (int i = 0; i < 32; i++) {
            ull o = __shfl_down_sync(0xffffffffu, acc[i], off, 16);
            float lo, hi, ol, oh;
            unpack2(acc[i], lo, hi); unpack2(o, ol, oh);
            acc[i] = pack2(lo + ol, hi + oh);
        }
    }
    if (sub == 0 && blk < NBLK8) {
        ull* dst = g_part2 + ((size_t)(b * NSPLIT + s) * NBLK8 + blk) * 32;
#pragma unroll
        for (int i = 0; i < 32; i++) dst[i] = acc[i];
    }
}

// ---------------- Kernel B: attention-layer math per batch ------------------

__global__ void __launch_bounds__(NTHREADS) kernel_b(
    const float* __restrict__ wq, const float* __restrict__ bq,
    const float* __restrict__ wk, const float* __restrict__ bk,
    const float* __restrict__ wv, const float* __restrict__ bv,
    const float* __restrict__ w1, const float* __restrict__ b1,
    const float* __restrict__ gamma, const float* __restrict__ beta,
    const float* __restrict__ mean, const float* __restrict__ var)
{
    __shared__ __align__(16) float smem[8][P][PP];
    float (*S)[PP]   = smem[0];
    float (*A)[PP]   = smem[1];
    float (*T1)[PP]  = smem[2];
    float (*G)[PP]   = smem[3];
    float (*M)[PP]   = smem[4];
    float (*W0)[PP]  = smem[5];
    float (*Wk_)[PP] = smem[6];
    float (*Wv_)[PP] = smem[7];

    int tid = threadIdx.x;
    int b   = blockIdx.x;

    // reconstruct S from blocked partials (sum 4 splits, mirror lower)
    const float* src = (const float*)(g_part2 + (size_t)b * NSPLIT * NBLK8 * 32);
    for (int i = tid; i < P * P; i += NTHREADS) {
        int r = i / P, c = i % P;
        int rr = r, cc = c;
        if (r > c) { rr = c; cc = r; }
        int bi = rr >> 3, bj = cc >> 3;
        int blkidx = bi * (11 - bi) / 2 + (bj - bi);
        int off = blkidx * 64 + (rr & 7) * 8 + (cc & 7);
        float v = src[off] + src[960 + off] + src[1920 + off] + src[2880 + off];
        S[r][c] = v;
    }
    __syncthreads();

    float scale = rsqrtf((float)TLEN);

    for (int layer = 0; layer < 3; layer++) {
        stage_w(W0,  wq + layer * CH * CH, bq + layer * CH, tid);
        stage_w(Wk_, wk + layer * CH * CH, bk + layer * CH, tid);
        stage_w(Wv_, wv + layer * CH * CH, bv + layer * CH, tid);

        mm_nn(T1, W0, S, tid);    // T1 = Wq' S
        mm_nt(G, T1, Wk_, tid);   // G  = Wq' S Wk'^T

        if (tid < CH) {
            float mx = -1e30f;
            for (int c = 0; c < CH; c++) mx = fmaxf(mx, G[tid][c] * scale);
            float sm = 0.f;
            for (int c = 0; c < CH; c++) {
                float e = expf(G[tid][c] * scale - mx);
                G[tid][c] = e; sm += e;
            }
            float inv = 1.f / sm;
            for (int c = 0; c < CH; c++) G[tid][c] *= inv;
            G[tid][34] = 0.f; G[tid][35] = 0.f;
        } else if (tid == CH) {
            for (int c = 0; c < PP; c++) { G[34][c] = 0.f; G[35][c] = 0.f; }
            G[34][34] = 1.f;
        }
        __syncthreads();

        mm_nn(M, G, Wv_, tid);    // M = attn' Wv''

        if (layer < 2) {          // S <- M S M^T
            mm_nn(T1, M, S, tid);
            mm_nt(S, T1, M, tid);
        }

        if (layer == 0) {
            for (int i = tid; i < P * PP; i += NTHREADS) (&A[0][0])[i] = (&M[0][0])[i];
            __syncthreads();
        } else if (layer == 1) {
            mm_nn(T1, M, A, tid); // A <- M2 * M1
            for (int i = tid; i < P * PP; i += NTHREADS) (&A[0][0])[i] = (&T1[0][0])[i];
            __syncthreads();
        } else {
            for (int i = tid; i < P * PP; i += NTHREADS) {
                int r = i / PP, c = i % PP;
                float v = 0.f;
                if (r < 16) {
                    float iv = gamma[r] * rsqrtf(var[r] + 1e-5f);
                    if (c < CH)       v = iv * w1[r * CH + c];
                    else if (c == CH) v = iv * (b1[r] - mean[r]) + beta[r];
                }
                W0[r][c] = v;
            }
            __syncthreads();
            mm_nn(T1, W0, M, tid); // R   = W1h * M3
            mm_nn(G, T1, A, tid);  // W1f = R * (M2 M1)
            for (int i = tid; i < 16 * 35; i += NTHREADS)
                g_W1f[b * 16 * 35 + i] = G[i / 35][i % 35];
        }
    }
}

// ---------------- Kernel C: pointwise head, 2 t per thread ------------------

__global__ void __launch_bounds__(CTH) kernel_c(
    const float* __restrict__ x,
    const float* __restrict__ w2, const float* __restrict__ b2,
    float* __restrict__ out)
{
    __shared__ __align__(16) float Hct[CH][HPITCH];  // transposed h
    __shared__ __align__(16) float Wt[35][16];       // transposed W1f
    __shared__ float w2s[48];
    __shared__ float b2s[3];

    int tid = threadIdx.x;
    int b   = blockIdx.y;
    int t0  = blockIdx.x * CTT;

    for (int i = tid; i < 16 * 35; i += CTH) {
        int c = i >> 4, o = i & 15;
        Wt[c][o] = g_W1f[b * 560 + o * 35 + c];
    }
    if (tid < 48) w2s[tid] = w2[tid];
    if (tid < 3)  b2s[tid] = b2[tid];

#pragma unroll
    for (int c = 0; c < 2; c++) {
        const float4* src = (const float4*)(x + ((size_t)(b * 2 + c) * TLEN + t0) * 17);
        for (int j = tid; j < CTT * 17 / 4; j += CTH) {
            float4 v = src[j];
            int idx = 4 * j;
            int t = idx / 17, vv = idx - 17 * t;
            float comp[4] = {v.x, v.y, v.z, v.w};
#pragma unroll
            for (int e = 0; e < 4; e++) {
                Hct[c * 17 + vv][t] = comp[e];
                vv++; if (vv == 17) { vv = 0; t++; }
            }
        }
    }
    __syncthreads();

    int tl = 2 * tid;
    ull u0[8], u1[8];
    {
        const ulonglong2* wb = (const ulonglong2*)&Wt[34][0];
#pragma unroll
        for (int p = 0; p < 4; p++) {
            ulonglong2 w = wb[p];
            u0[2 * p] = w.x; u0[2 * p + 1] = w.y;
            u1[2 * p] = w.x; u1[2 * p + 1] = w.y;
        }
    }
#pragma unroll
    for (int c = 0; c < CH; c++) {
        float2 h2 = *(const float2*)&Hct[c][tl];
        ull h0 = pack2(h2.x, h2.x), h1 = pack2(h2.y, h2.y);
        const ulonglong2* wr = (const ulonglong2*)&Wt[c][0];
#pragma unroll
        for (int p = 0; p < 4; p++) {
            ulonglong2 w = wr[p];
            fma2(u0[2 * p],     w.x, h0); fma2(u0[2 * p + 1], w.y, h0);
            fma2(u1[2 * p],     w.x, h1); fma2(u1[2 * p + 1], w.y, h1);
        }
    }

    float f0[16], f1[16];
#pragma unroll
    for (int p = 0; p < 8; p++) {
        unpack2(u0[p], f0[2 * p], f0[2 * p + 1]);
        unpack2(u1[p], f1[2 * p], f1[2 * p + 1]);
    }
#pragma unroll
    for (int o = 0; o < 16; o++) {
        f0[o] = (f0[o] > 0.f) ? f0[o] : 0.01f * f0[o];
        f1[o] = (f1[o] > 0.f) ? f1[o] : 0.01f * f1[o];
    }

#pragma unroll
    for (int j = 0; j < 3; j++) {
        float s0 = b2s[j], s1 = b2s[j];
#pragma unroll
        for (int o = 0; o < 16; o++) {
            s0 += w2s[j * 16 + o] * f0[o];
            s1 += w2s[j * 16 + o] * f1[o];
        }
        *(float2*)&out[(size_t)(b * 3 + j) * TLEN + t0 + tl] = make_float2(s0, s1);
    }
}

// ---------------------------------------------------------------------------

extern "C" void kernel_launch(void* const* d_in, const int* in_sizes, int n_in,
                              void* d_out, int out_size) {
    const float* x     = (const float*)d_in[0];
    const float* wq    = (const float*)d_in[1];
    const float* bq    = (const float*)d_in[2];
    const float* wk    = (const float*)d_in[3];
    const float* bk    = (const float*)d_in[4];
    const float* wv    = (const float*)d_in[5];
    const float* bv    = (const float*)d_in[6];
    const float* w1    = (const float*)d_in[7];
    const float* b1    = (const float*)d_in[8];
    const float* gamma = (const float*)d_in[9];
    const float* beta  = (const float*)d_in[10];
    const float* mean  = (const float*)d_in[11];
    const float* var   = (const float*)d_in[12];
    const float* w2    = (const float*)d_in[13];
    const float* b2    = (const float*)d_in[14];
    float* out = (float*)d_out;

    dim3 gg(BATCH, NSPLIT);
    kernel_gram<<<gg, NTHREADS>>>(x);
    kernel_b<<<BATCH, NTHREADS>>>(wq, bq, wk, bk, wv, bv,
                                  w1, b1, gamma, beta, mean, var);
    dim3 gc(TLEN / CTT, BATCH);
    kernel_c<<<gc, CTH>>>(x, w2, b2, out);
}

// round 10
// speedup vs baseline: 1.1825x; 1.1825x over previous
#include <cuda_runtime.h>

#define BATCH    512
#define TLEN     2048
#define CH       34      // true channel count (2*17)
#define P        36      // padded homogeneous dim
#define PP       37      // kernel_b / gram-S row pitch
#define TT       128     // t-tile for Gram phase
#define NTHREADS 256     // gram threads
#define NTB      512     // kernel_b threads
#define TG       5       // gram t-phases per block
#define NBLK     45      // symmetric 4x4 blocks over 36 (9x9 grid, bc >= br)
#define NSPLIT   4
#define TSPLIT   (TLEN / NSPLIT)
#define CTT3     128     // kernel_c t-tile (= threads, 1 t per thread)

typedef unsigned long long ull;

// Per-batch fused head matrix: W1f[b][16][35] (homogeneous: col 34 = bias)
__device__ float g_W1f[BATCH * 16 * 35];
// Partial Gram matrices: g_part[b][s][36][36]
__device__ float g_part[BATCH * NSPLIT * P * P];

// ---------------- packed f32x2 helpers (sm_103a FFMA2) ----------------------

__device__ __forceinline__ ull pack2(float lo, float hi) {
    ull r; asm("mov.b64 %0, {%1, %2};" : "=l"(r) : "f"(lo), "f"(hi)); return r;
}
__device__ __forceinline__ void unpack2(ull v, float& lo, float& hi) {
    asm("mov.b64 {%0, %1}, %2;" : "=f"(lo), "=f"(hi) : "l"(v));
}
__device__ __forceinline__ void fma2(ull& d, ull a, ull b) {
    asm("fma.rn.f32x2 %0, %1, %2, %0;" : "+l"(d) : "l"(a), "l"(b));
}

// ---------------- 36x36 shared-memory matmuls (432 active threads) ----------

__device__ __forceinline__ void mm_nn(float (*D)[PP], const float (*A)[PP],
                                      const float (*B)[PP], int tid) {
    if (tid < 432) {
        int r  = tid % P;
        int c0 = (tid / P) * 3;
        float a0 = 0.f, a1 = 0.f, a2 = 0.f;
#pragma unroll
        for (int k = 0; k < P; k++) {
            float a = A[r][k];
            a0 += a * B[k][c0 + 0];
            a1 += a * B[k][c0 + 1];
            a2 += a * B[k][c0 + 2];
        }
        D[r][c0 + 0] = a0; D[r][c0 + 1] = a1; D[r][c0 + 2] = a2;
    }
    __syncthreads();
}

__device__ __forceinline__ void mm_nt(float (*D)[PP], const float (*A)[PP],
                                      const float (*B)[PP], int tid) {
    if (tid < 432) {
        int r  = tid % P;
        int c0 = (tid / P) * 3;
        float a0 = 0.f, a1 = 0.f, a2 = 0.f;
#pragma unroll
        for (int k = 0; k < P; k++) {
            float a = A[r][k];
            a0 += a * B[c0 + 0][k];
            a1 += a * B[c0 + 1][k];
            a2 += a * B[c0 + 2][k];
        }
        D[r][c0 + 0] = a0; D[r][c0 + 1] = a1; D[r][c0 + 2] = a2;
    }
    __syncthreads();
}

__device__ __forceinline__ void stage_w(float (*W)[PP], const float* __restrict__ w,
                                        const float* __restrict__ bias, int tid) {
    for (int i = tid; i < P * PP; i += NTB) {
        int r = i / PP, c = i % PP;
        float v = 0.f;
        if (r < CH && c < CH)       v = w[r * CH + c];
        else if (r < CH && c == CH) v = bias[r];
        else if (r == CH && c == CH) v = 1.f;
        W[r][c] = v;
    }
    __syncthreads();
}

// ---------------- Kernel GRAM: partial S over a t-split, 4x4 blocks ---------

#define GRAM_STEP(t) do {                                         \
    float4 av = *(const float4*)&Hs[t][4 * br];                   \
    ulonglong2 bb = *(const ulonglong2*)&Hs[t][4 * bc];           \
    ull a0 = pack2(av.x, av.x), a1 = pack2(av.y, av.y);           \
    ull a2 = pack2(av.z, av.z), a3 = pack2(av.w, av.w);           \
    fma2(acc[0], a0, bb.x); fma2(acc[1], a0, bb.y);               \
    fma2(acc[2], a1, bb.x); fma2(acc[3], a1, bb.y);               \
    fma2(acc[4], a2, bb.x); fma2(acc[5], a2, bb.y);               \
    fma2(acc[6], a3, bb.x); fma2(acc[7], a3, bb.y);               \
} while (0)

__global__ void __launch_bounds__(NTHREADS, 4) kernel_gram(const float* __restrict__ x)
{
    __shared__ float S[P][PP];
    __shared__ __align__(16) float Hs[TT][P];

    int tid = threadIdx.x;
    int b   = blockIdx.x;
    int s   = blockIdx.y;

    for (int i = tid; i < P * PP; i += NTHREADS) (&S[0][0])[i] = 0.f;

    bool act = (tid < NBLK * TG);
    int br = 0, bc = 0, sub = 0;
    if (act) {
        int blk = tid / TG;
        sub = tid % TG;
        int k = blk, r = 0;
        while (k >= 9 - r) { k -= 9 - r; r++; }
        br = r; bc = r + k;
    }
    ull acc[8];
#pragma unroll
    for (int i = 0; i < 8; i++) acc[i] = 0ull;

    const float* xb = x + (size_t)b * 2 * TLEN * 17;
    int tbase = s * TSPLIT;

    for (int t0 = tbase; t0 < tbase + TSPLIT; t0 += TT) {
        __syncthreads();
        // coalesced float4 stage -> Hs[t][ch], ch = c*17+v
#pragma unroll
        for (int c = 0; c < 2; c++) {
            const float4* src = (const float4*)(xb + (size_t)c * TLEN * 17 + (size_t)t0 * 17);
            for (int j = tid; j < TT * 17 / 4; j += NTHREADS) {
                float4 v = src[j];
                int idx = 4 * j;
                int t = idx / 17, vv = idx - 17 * t;
                float comp[4] = {v.x, v.y, v.z, v.w};
#pragma unroll
                for (int e = 0; e < 4; e++) {
                    Hs[t][c * 17 + vv] = comp[e];
                    vv++; if (vv == 17) { vv = 0; t++; }
                }
            }
        }
        for (int i = tid; i < TT; i += NTHREADS) { Hs[i][34] = 1.f; Hs[i][35] = 0.f; }
        __syncthreads();

        if (act) {
            int t = sub;
            for (; t + TG < TT; t += 2 * TG) {      // 2-t unroll for ILP
                GRAM_STEP(t);
                GRAM_STEP(t + TG);
            }
            if (t < TT) GRAM_STEP(t);
        }
    }
    __syncthreads();
    if (act) {
#pragma unroll
        for (int i = 0; i < 4; i++) {
            float v0, v1, v2, v3;
            unpack2(acc[2 * i + 0], v0, v1);
            unpack2(acc[2 * i + 1], v2, v3);
            atomicAdd(&S[4 * br + i][4 * bc + 0], v0);
            atomicAdd(&S[4 * br + i][4 * bc + 1], v1);
            atomicAdd(&S[4 * br + i][4 * bc + 2], v2);
            atomicAdd(&S[4 * br + i][4 * bc + 3], v3);
        }
    }
    __syncthreads();
    // mirror lower triangle
    for (int i = tid; i < P * P; i += NTHREADS) {
        int r = i / P, c = i % P;
        if (r > c) S[r][c] = S[c][r];
    }
    __syncthreads();
    float* dst = g_part + (size_t)(b * NSPLIT + s) * P * P;
    for (int i = tid; i < P * P; i += NTHREADS) dst[i] = S[i / P][i % P];
}

// ---------------- Kernel B: attention-layer math per batch (512 thr) --------

__global__ void __launch_bounds__(NTB) kernel_b(
    const float* __restrict__ wq, const float* __restrict__ bq,
    const float* __restrict__ wk, const float* __restrict__ bk,
    const float* __restrict__ wv, const float* __restrict__ bv,
    const float* __restrict__ w1, const float* __restrict__ b1,
    const float* __restrict__ gamma, const float* __restrict__ beta,
    const float* __restrict__ mean, const float* __restrict__ var)
{
    __shared__ __align__(16) float smem[8][P][PP];
    float (*S)[PP]   = smem[0];
    float (*A)[PP]   = smem[1];
    float (*T1)[PP]  = smem[2];
    float (*G)[PP]   = smem[3];
    float (*M)[PP]   = smem[4];
    float (*W0)[PP]  = smem[5];
    float (*Wk_)[PP] = smem[6];
    float (*Wv_)[PP] = smem[7];

    int tid = threadIdx.x;
    int b   = blockIdx.x;

    // sum the 4 Gram partials
    const float* src = g_part + (size_t)b * NSPLIT * P * P;
    for (int i = tid; i < P * P; i += NTB) {
        float v = src[i] + src[P * P + i] + src[2 * P * P + i] + src[3 * P * P + i];
        S[i / P][i % P] = v;
    }
    __syncthreads();

    float scale = rsqrtf((float)TLEN);

    for (int layer = 0; layer < 3; layer++) {
        stage_w(W0,  wq + layer * CH * CH, bq + layer * CH, tid);
        stage_w(Wk_, wk + layer * CH * CH, bk + layer * CH, tid);
        stage_w(Wv_, wv + layer * CH * CH, bv + layer * CH, tid);

        mm_nn(T1, W0, S, tid);    // T1 = Wq' S
        mm_nt(G, T1, Wk_, tid);   // G  = Wq' S Wk'^T

        if (tid < CH) {
            float mx = -1e30f;
            for (int c = 0; c < CH; c++) mx = fmaxf(mx, G[tid][c] * scale);
            float sm = 0.f;
            for (int c = 0; c < CH; c++) {
                float e = expf(G[tid][c] * scale - mx);
                G[tid][c] = e; sm += e;
            }
            float inv = 1.f / sm;
            for (int c = 0; c < CH; c++) G[tid][c] *= inv;
            G[tid][34] = 0.f; G[tid][35] = 0.f;
        } else if (tid == CH) {
            for (int c = 0; c < PP; c++) { G[34][c] = 0.f; G[35][c] = 0.f; }
            G[34][34] = 1.f;
        }
        __syncthreads();

        mm_nn(M, G, Wv_, tid);    // M = attn' Wv''

        if (layer < 2) {          // S <- M S M^T
            mm_nn(T1, M, S, tid);
            mm_nt(S, T1, M, tid);
        }

        if (layer == 0) {
            for (int i = tid; i < P * PP; i += NTB) (&A[0][0])[i] = (&M[0][0])[i];
            __syncthreads();
        } else if (layer == 1) {
            mm_nn(T1, M, A, tid); // A <- M2 * M1
            for (int i = tid; i < P * PP; i += NTB) (&A[0][0])[i] = (&T1[0][0])[i];
            __syncthreads();
        } else {
            for (int i = tid; i < P * PP; i += NTB) {
                int r = i / PP, c = i % PP;
                float v = 0.f;
                if (r < 16) {
                    float iv = gamma[r] * rsqrtf(var[r] + 1e-5f);
                    if (c < CH)       v = iv * w1[r * CH + c];
                    else if (c == CH) v = iv * (b1[r] - mean[r]) + beta[r];
                }
                W0[r][c] = v;
            }
            __syncthreads();
            mm_nn(T1, W0, M, tid); // R   = W1h * M3
            mm_nn(G, T1, A, tid);  // W1f = R * (M2 M1)
            for (int i = tid; i < 16 * 35; i += NTB)
                g_W1f[b * 16 * 35 + i] = G[i / 35][i % 35];
        }
    }
}

// ---------------- Kernel C: pointwise head, 1 t per thread, high occ --------

__global__ void __launch_bounds__(CTT3) kernel_c(
    const float* __restrict__ x,
    const float* __restrict__ w2, const float* __restrict__ b2,
    float* __restrict__ out)
{
    __shared__ float Hs[CTT3][35];               // Hs[t][ch], odd pitch -> conflict-free
    __shared__ __align__(16) float Wt[35][16];   // transposed W1f: Wt[c][o]
    __shared__ float w2s[48];
    __shared__ float b2s[3];

    int tid = threadIdx.x;
    int b   = blockIdx.y;
    int t0  = blockIdx.x * CTT3;

    for (int i = tid; i < 16 * 35; i += CTT3) {
        int c = i >> 4, o = i & 15;
        Wt[c][o] = g_W1f[b * 560 + o * 35 + c];
    }
    if (tid < 48) w2s[tid] = w2[tid];
    if (tid < 3)  b2s[tid] = b2[tid];

#pragma unroll
    for (int c = 0; c < 2; c++) {
        const float4* src = (const float4*)(x + ((size_t)(b * 2 + c) * TLEN + t0) * 17);
        for (int j = tid; j < CTT3 * 17 / 4; j += CTT3) {
            float4 v = src[j];
            int idx = 4 * j;
            int t = idx / 17, vv = idx - 17 * t;
            float comp[4] = {v.x, v.y, v.z, v.w};
#pragma unroll
            for (int e = 0; e < 4; e++) {
                Hs[t][c * 17 + vv] = comp[e];
                vv++; if (vv == 17) { vv = 0; t++; }
            }
        }
    }
    __syncthreads();

    // init accumulators with the homogeneous bias row (16 floats = 8 ulls)
    ull u[8];
    {
        const ull* wb = (const ull*)&Wt[34][0];
#pragma unroll
        for (int p = 0; p < 8; p++) u[p] = wb[p];
    }

#pragma unroll
    for (int c = 0; c < CH; c++) {
        float hv = Hs[tid][c];
        ull hh = pack2(hv, hv);
        const ulonglong2* wr = (const ulonglong2*)&Wt[c][0];
        ulonglong2 wa = wr[0], wbv = wr[1];
        fma2(u[0], wa.x,  hh); fma2(u[1], wa.y,  hh);
        fma2(u[2], wbv.x, hh); fma2(u[3], wbv.y, hh);
    }
    // second half of the 16 outputs in a separate pass keeps live regs low
#pragma unroll
    for (int c = 0; c < CH; c++) {
        float hv = Hs[tid][c];
        ull hh = pack2(hv, hv);
        const ulonglong2* wr = (const ulonglong2*)&Wt[c][8];
        ulonglong2 wc = wr[0], wd = wr[1];
        fma2(u[4], wc.x, hh); fma2(u[5], wc.y, hh);
        fma2(u[6], wd.x, hh); fma2(u[7], wd.y, hh);
    }

    float f[16];
#pragma unroll
    for (int p = 0; p < 8; p++) unpack2(u[p], f[2 * p], f[2 * p + 1]);
#pragma unroll
    for (int o = 0; o < 16; o++) f[o] = (f[o] > 0.f) ? f[o] : 0.01f * f[o];

#pragma unroll
    for (int j = 0; j < 3; j++) {
        float sv = b2s[j];
#pragma unroll
        for (int o = 0; o < 16; o++) sv += w2s[j * 16 + o] * f[o];
        out[(size_t)(b * 3 + j) * TLEN + t0 + tid] = sv;
    }
}

// ---------------------------------------------------------------------------

extern "C" void kernel_launch(void* const* d_in, const int* in_sizes, int n_in,
                              void* d_out, int out_size) {
    const float* x     = (const float*)d_in[0];
    const float* wq    = (const float*)d_in[1];
    const float* bq    = (const float*)d_in[2];
    const float* wk    = (const float*)d_in[3];
    const float* bk    = (const float*)d_in[4];
    const float* wv    = (const float*)d_in[5];
    const float* bv    = (const float*)d_in[6];
    const float* w1    = (const float*)d_in[7];
    const float* b1    = (const float*)d_in[8];
    const float* gamma = (const float*)d_in[9];
    const float* beta  = (const float*)d_in[10];
    const float* mean  = (const float*)d_in[11];
    const float* var   = (const float*)d_in[12];
    const float* w2    = (const float*)d_in[13];
    const float* b2    = (const float*)d_in[14];
    float* out = (float*)d_out;

    dim3 gg(BATCH, NSPLIT);
    kernel_gram<<<gg, NTHREADS>>>(x);
    kernel_b<<<BATCH, NTB>>>(wq, bq, wk, bk, wv, bv,
                             w1, b1, gamma, beta, mean, var);
    dim3 gc(TLEN / CTT3, BATCH);
    kernel_c<<<gc, CTT3>>>(x, w2, b2, out);
}